// round 5
// baseline (speedup 1.0000x reference)
#include <cuda_runtime.h>
#include <cuda_fp16.h>
#include <stdint.h>
#include <math.h>

// Problem constants
#define BB   2
#define SS   2048
#define HID  4096
#define NH   32
#define NKV  8
#define DD   128
#define TT   (BB*SS)       // 4096 tokens

// ---------------- scratch (device globals) ----------------
__device__ float g_q   [(size_t)TT * HID];
__device__ float g_k   [(size_t)TT * (NKV*DD)];
__device__ float g_v   [(size_t)TT * (NKV*DD)];

__device__ __half g_Xhi[(size_t)TT * HID];
__device__ __half g_Xlo[(size_t)TT * HID];
__device__ __half g_Ahi[(size_t)TT * HID];
__device__ __half g_Alo[(size_t)TT * HID];
__device__ __half g_Wqt_hi[(size_t)HID * HID];
__device__ __half g_Wqt_lo[(size_t)HID * HID];
__device__ __half g_Wkt_hi[(size_t)HID * (NKV*DD)];
__device__ __half g_Wkt_lo[(size_t)HID * (NKV*DD)];
__device__ __half g_Wvt_hi[(size_t)HID * (NKV*DD)];
__device__ __half g_Wvt_lo[(size_t)HID * (NKV*DD)];
__device__ __half g_Wot_hi[(size_t)HID * HID];
__device__ __half g_Wot_lo[(size_t)HID * HID];

// flash operands (fp16 hi/lo)
__device__ __half g_Qfhi[(size_t)TT * (NH*DD)];
__device__ __half g_Qflo[(size_t)TT * (NH*DD)];
__device__ __half g_Kfhi[(size_t)TT * (NKV*DD)];
__device__ __half g_Kflo[(size_t)TT * (NKV*DD)];
__device__ __half g_VThi[(size_t)TT * (NKV*DD)];   // [b,kh,d,s]
__device__ __half g_VTlo[(size_t)TT * (NKV*DD)];

// ---------------- PTX helpers (baseline features only) ----------------
__device__ __forceinline__ uint32_t smem_u32(const void* p) {
    uint32_t a;
    asm("{ .reg .u64 t; cvta.to.shared.u64 t, %1; cvt.u32.u64 %0, t; }" : "=r"(a) : "l"(p));
    return a;
}

#define CP16(dst, src) \
    asm volatile("cp.async.cg.shared.global [%0], [%1], 16;" :: "r"(dst), "l"(src) : "memory")
#define CP_COMMIT() asm volatile("cp.async.commit_group;" ::: "memory")
#define CP_WAIT_0() asm volatile("cp.async.wait_group 0;" ::: "memory")
#define CP_WAIT_1() asm volatile("cp.async.wait_group 1;" ::: "memory")

#define LDM_X4(r0, r1, r2, r3, addr) \
    asm volatile("ldmatrix.sync.aligned.m8n8.x4.shared.b16 {%0,%1,%2,%3}, [%4];" \
        : "=r"(r0), "=r"(r1), "=r"(r2), "=r"(r3) : "r"(addr))

__device__ __forceinline__ void mma16816(float* d, const uint32_t* a, const uint32_t* b) {
    asm volatile("mma.sync.aligned.m16n8k16.row.col.f32.f16.f16.f32 "
        "{%0,%1,%2,%3}, {%4,%5,%6,%7}, {%8,%9}, {%0,%1,%2,%3};"
        : "+f"(d[0]), "+f"(d[1]), "+f"(d[2]), "+f"(d[3])
        : "r"(a[0]), "r"(a[1]), "r"(a[2]), "r"(a[3]), "r"(b[0]), "r"(b[1]));
}

__device__ __forceinline__ float ex2(float x) {
    float r; asm("ex2.approx.f32 %0, %1;" : "=f"(r) : "f"(x)); return r;
}
__device__ __forceinline__ uint32_t f22u(float a, float b) {
    __half2 h = __floats2half2_rn(a, b);
    return *(uint32_t*)&h;
}

// ---------------- split / transpose prep kernels (fp16 hi/lo) ----------------
__global__ void split_kernel(const float* __restrict__ X,
                             __half* __restrict__ H, __half* __restrict__ L)
{
    size_t i = ((size_t)blockIdx.x * blockDim.x + threadIdx.x) * 4;
    float4 v = *(const float4*)(X + i);
    __align__(8) __half h[4], l[4];
    float vv[4] = {v.x, v.y, v.z, v.w};
#pragma unroll
    for (int j = 0; j < 4; j++) {
        h[j] = __float2half_rn(vv[j]);
        l[j] = __float2half_rn(vv[j] - __half2float(h[j]));
    }
    *(uint2*)(H + i) = *(uint2*)h;
    *(uint2*)(L + i) = *(uint2*)l;
}

// W [Kd, Nd] row-major -> Th/Tl [Nd, Kd] fp16 hi/lo
__global__ void transpose_split_kernel(const float* __restrict__ W,
                                       __half* __restrict__ Th, __half* __restrict__ Tl,
                                       int Kd, int Nd)
{
    __shared__ float tile[32][33];
    int n0 = blockIdx.x * 32, k0 = blockIdx.y * 32;
    int tx = threadIdx.x, ty = threadIdx.y;
#pragma unroll
    for (int i = 0; i < 4; i++)
        tile[ty + 8*i][tx] = W[(size_t)(k0 + ty + 8*i) * Nd + n0 + tx];
    __syncthreads();
#pragma unroll
    for (int i = 0; i < 4; i++) {
        float v = tile[tx][ty + 8*i];
        __half h = __float2half_rn(v);
        __half l = __float2half_rn(v - __half2float(h));
        size_t o = (size_t)(n0 + ty + 8*i) * Kd + k0 + tx;
        Th[o] = h; Tl[o] = l;
    }
}

// ---------------- mma.sync fp16-split GEMM, 128x256x64, warp tile 64x64 ----------------
#define GBM 128
#define GBN 256
#define GBK 64
#define S2_AH 0
#define S2_AL 16384
#define S2_BH 32768
#define S2_BL 65536
#define S2_SZ 98304
#define GEMM_SMEM_TOTAL (2*S2_SZ)   // 196608

__global__ __launch_bounds__(256, 1) void hgemm3_kernel(
    const __half* __restrict__ Ahi, const __half* __restrict__ Alo,
    const __half* __restrict__ Bhi, const __half* __restrict__ Blo,
    float* __restrict__ C, int M, int N, int K)
{
    extern __shared__ __align__(128) char smem[];
    const uint32_t sbase = smem_u32(smem);
    const int tid = threadIdx.x;
    const int lane = tid & 31;
    const int wid = tid >> 5;
    const int wm = wid >> 2;       // 0..1 (64 rows each)
    const int wn = wid & 3;        // 0..3 (64 cols each)

    const size_t arow0 = (size_t)blockIdx.y * GBM;
    const size_t brow0 = (size_t)blockIdx.x * GBN;
    const __half* Ah = Ahi + arow0 * K;
    const __half* Al = Alo + arow0 * K;
    const __half* Bh = Bhi + brow0 * K;
    const __half* Bl = Blo + brow0 * K;

    const int NC = K / GBK;
    const int lrow = tid >> 3;          // 0..31
    const int lc   = tid & 7;

    // load one stage: A 128 rows, B 256 rows; 128B per row; hi & lo
    #define LOAD_STAGE(st, koff)                                                 \
    do {                                                                         \
        uint32_t s0 = sbase + (st) * S2_SZ;                                      \
        _Pragma("unroll")                                                        \
        for (int i = 0; i < 4; i++) {                                            \
            int row = lrow + i * 32;                                             \
            uint32_t off = (uint32_t)(row * 128 + ((lc ^ (row & 7)) << 4));      \
            size_t go = (size_t)row * K + (koff) + lc * 8;                       \
            CP16(s0 + S2_AH + off, Ah + go);                                     \
            CP16(s0 + S2_AL + off, Al + go);                                     \
        }                                                                        \
        _Pragma("unroll")                                                        \
        for (int i = 0; i < 8; i++) {                                            \
            int row = lrow + i * 32;                                             \
            uint32_t off = (uint32_t)(row * 128 + ((lc ^ (row & 7)) << 4));      \
            size_t go = (size_t)row * K + (koff) + lc * 8;                       \
            CP16(s0 + S2_BH + off, Bh + go);                                     \
            CP16(s0 + S2_BL + off, Bl + go);                                     \
        }                                                                        \
        CP_COMMIT();                                                             \
    } while (0)

    LOAD_STAGE(0, 0);

    float acc[4][8][4];
#pragma unroll
    for (int mt = 0; mt < 4; mt++)
#pragma unroll
        for (int nt = 0; nt < 8; nt++)
#pragma unroll
            for (int j = 0; j < 4; j++) acc[mt][nt][j] = 0.f;

    const int g  = lane >> 3;
    const int r8 = lane & 7;

    for (int c = 0; c < NC; c++) {
        if (c + 1 < NC) { LOAD_STAGE((c + 1) & 1, (c + 1) * GBK); CP_WAIT_1(); }
        else            { CP_WAIT_0(); }
        __syncthreads();

        const uint32_t sA = sbase + (c & 1) * S2_SZ;
        const uint32_t sB = sA + S2_BH;

#pragma unroll
        for (int ks = 0; ks < 4; ks++) {
            uint32_t ah[4][4], al[4][4];
#pragma unroll
            for (int mt = 0; mt < 4; mt++) {
                int arow = wm * 64 + mt * 16 + (g & 1) * 8 + r8;
                int kc = ks * 2 + (g >> 1);
                uint32_t addr = sA + (uint32_t)(arow * 128 + ((kc ^ (arow & 7)) << 4));
                LDM_X4(ah[mt][0], ah[mt][1], ah[mt][2], ah[mt][3], addr);
                LDM_X4(al[mt][0], al[mt][1], al[mt][2], al[mt][3], addr + S2_AL);
            }
            uint32_t bh[8][2], bl[8][2];
#pragma unroll
            for (int pr = 0; pr < 4; pr++) {
                int bn = wn * 64 + pr * 16 + (g >> 1) * 8 + r8;
                int kc = ks * 2 + (g & 1);
                uint32_t addr = sB + (uint32_t)(bn * 128 + ((kc ^ (bn & 7)) << 4));
                uint32_t t0, t1, t2, t3;
                LDM_X4(t0, t1, t2, t3, addr);
                bh[pr*2][0] = t0; bh[pr*2][1] = t1; bh[pr*2+1][0] = t2; bh[pr*2+1][1] = t3;
                LDM_X4(t0, t1, t2, t3, addr + 32768);   // BL - BH
                bl[pr*2][0] = t0; bl[pr*2][1] = t1; bl[pr*2+1][0] = t2; bl[pr*2+1][1] = t3;
            }
#pragma unroll
            for (int mt = 0; mt < 4; mt++)
#pragma unroll
                for (int nt = 0; nt < 8; nt++) {
                    mma16816(acc[mt][nt], ah[mt], bh[nt]);
                    mma16816(acc[mt][nt], al[mt], bh[nt]);
                    mma16816(acc[mt][nt], ah[mt], bl[nt]);
                }
        }
        __syncthreads();
    }

    const int er = lane >> 2;
    const int ec = (lane & 3) * 2;
#pragma unroll
    for (int mt = 0; mt < 4; mt++) {
        size_t m0 = arow0 + wm * 64 + mt * 16 + er;
#pragma unroll
        for (int nt = 0; nt < 8; nt++) {
            size_t n0 = brow0 + wn * 64 + nt * 8 + ec;
            *(float2*)(C + m0 * N + n0)       = make_float2(acc[mt][nt][0], acc[mt][nt][1]);
            *(float2*)(C + (m0 + 8) * N + n0) = make_float2(acc[mt][nt][2], acc[mt][nt][3]);
        }
    }
    #undef LOAD_STAGE
}

// ---------------- RoPE kernels -> fp16 hi/lo ----------------
// Q scale folds 1/sqrt(D) AND log2(e) so flash uses exp2 directly.
#define QSCALE 0.12751744951953698f

__global__ void rope_q_f16(const float* __restrict__ cq,
                           const float* __restrict__ cosc,
                           const float* __restrict__ sinc,
                           __half* __restrict__ Qhi, __half* __restrict__ Qlo)
{
    int idx = blockIdx.x * blockDim.x + threadIdx.x;
    int d = idx & 127;
    int h = (idx >> 7) & 31;
    int t = idx >> 12;
    int s = t & (SS - 1);
    int b = t >> 11;
    float v  = cq[idx];
    float vp = cq[idx ^ 64];
    float rot = (d < 64) ? -vp : vp;
    float c  = cosc[s * DD + d];
    float sn = sinc[s * DD + d];
    float val = (v * c + rot * sn) * QSCALE;
    __half hi = __float2half_rn(val);
    __half lo = __float2half_rn(val - __half2float(hi));
    size_t o = (((size_t)(b * NH + h)) * SS + s) * DD + d;
    Qhi[o] = hi; Qlo[o] = lo;
}

__global__ void rope_k_f16(const float* __restrict__ ck,
                           const float* __restrict__ cosc,
                           const float* __restrict__ sinc,
                           __half* __restrict__ Khi, __half* __restrict__ Klo)
{
    int idx = blockIdx.x * blockDim.x + threadIdx.x;
    int d  = idx & 127;
    int kh = (idx >> 7) & 7;
    int t  = idx >> 10;
    int s = t & (SS - 1);
    int b = t >> 11;
    float v  = ck[idx];
    float vp = ck[idx ^ 64];
    float rot = (d < 64) ? -vp : vp;
    float c  = cosc[s * DD + d];
    float sn = sinc[s * DD + d];
    float val = v * c + rot * sn;
    __half hi = __float2half_rn(val);
    __half lo = __float2half_rn(val - __half2float(hi));
    size_t o = (((size_t)(b * NKV + kh)) * SS + s) * DD + d;
    Khi[o] = hi; Klo[o] = lo;
}

// V [token][kh*128+d] fp32 -> VT [b,kh,d,s] fp16 hi/lo
__global__ void transpose_v_f16(const float* __restrict__ v,
                                __half* __restrict__ VThi, __half* __restrict__ VTlo)
{
    __shared__ float tile[32][33];
    int s0 = blockIdx.x * 32;
    int d0 = blockIdx.y * 32;
    int bk = blockIdx.z;              // b*NKV + kh
    int b = bk >> 3, kh = bk & 7;
    int tx = threadIdx.x, ty = threadIdx.y;
#pragma unroll
    for (int i = 0; i < 4; i++) {
        int sj = ty + i * 8;
        tile[sj][tx] = v[((size_t)(b * SS + s0 + sj)) * (NKV*DD) + kh * DD + d0 + tx];
    }
    __syncthreads();
#pragma unroll
    for (int i = 0; i < 4; i++) {
        int dj = ty + i * 8;
        float val = tile[tx][dj];
        __half hi = __float2half_rn(val);
        __half lo = __float2half_rn(val - __half2float(hi));
        size_t o = ((size_t)bk * DD + d0 + dj) * SS + s0 + tx;
        VThi[o] = hi; VTlo[o] = lo;
    }
}

// ---------------- Flash attention (mma.sync fp16 split) ----------------
#define FQ_HI 0
#define FQ_LO 32768
#define FSTG0 65536
#define FK_HI 0
#define FK_LO 16384
#define FV_HI 32768
#define FV_LO 49152
#define FSTG_SZ 65536
#define FLASH_SMEM (FSTG0 + 2*FSTG_SZ)   // 196608

__device__ __forceinline__ uint32_t off256(int r, int kc) {
    return (uint32_t)(r * 256 + (((kc & 7) ^ (r & 7)) << 4) + ((kc >> 3) << 7));
}
__device__ __forceinline__ uint32_t off128(int r, int ck) {
    return (uint32_t)(r * 128 + ((ck ^ (r & 7)) << 4));
}

__global__ __launch_bounds__(256, 1) void flash_mma_kernel(
    const __half* __restrict__ Qhi, const __half* __restrict__ Qlo,
    const __half* __restrict__ Khi, const __half* __restrict__ Klo,
    const __half* __restrict__ VThi, const __half* __restrict__ VTlo,
    __half* __restrict__ Ohi, __half* __restrict__ Olo)
{
    extern __shared__ __align__(128) char smf[];
    const uint32_t sb = smem_u32(smf);
    const int qblk = blockIdx.x;
    const int h    = blockIdx.y;
    const int b    = blockIdx.z;
    const int kh   = h >> 2;
    const size_t bh  = (size_t)(b * NH + h);
    const size_t bkv = (size_t)(b * NKV + kh);
    const int tid = threadIdx.x, lane = tid & 31, w = tid >> 5;
    const int q0 = qblk * 128;
    const int g  = lane >> 3;
    const int r8 = lane & 7;

    #define LOAD_KV(stgof, ktv)                                                   \
    do {                                                                          \
        _Pragma("unroll")                                                         \
        for (int i = 0; i < 4; i++) {                                             \
            int idx = tid + i * 256;                                              \
            int key = idx >> 4, kc = idx & 15;                                    \
            uint32_t so = off256(key, kc);                                        \
            size_t gk = (bkv * SS + (size_t)(ktv) * 64 + key) * DD + kc * 8;      \
            CP16(sb + (stgof) + FK_HI + so, Khi + gk);                            \
            CP16(sb + (stgof) + FK_LO + so, Klo + gk);                            \
            int dd = idx >> 3, ck = idx & 7;                                      \
            uint32_t so2 = off128(dd, ck);                                        \
            size_t gv = (bkv * DD + dd) * SS + (size_t)(ktv) * 64 + ck * 8;       \
            CP16(sb + (stgof) + FV_HI + so2, VThi + gv);                          \
            CP16(sb + (stgof) + FV_LO + so2, VTlo + gv);                          \
        }                                                                         \
        CP_COMMIT();                                                              \
    } while (0)

#pragma unroll
    for (int i = 0; i < 8; i++) {
        int idx = tid + i * 256;
        int q = idx >> 4, kc = idx & 15;
        uint32_t so = off256(q, kc);
        size_t go = (bh * SS + q0 + q) * DD + kc * 8;
        CP16(sb + FQ_HI + so, Qhi + go);
        CP16(sb + FQ_LO + so, Qlo + go);
    }
    CP_COMMIT();
    LOAD_KV(FSTG0, 0);
    CP_WAIT_0();
    __syncthreads();

    uint32_t qh[8][4], ql[8][4];
#pragma unroll
    for (int ks = 0; ks < 8; ks++) {
        int qr = w * 16 + (g & 1) * 8 + r8;
        int kc = ks * 2 + (g >> 1);
        uint32_t ad = sb + off256(qr, kc);
        LDM_X4(qh[ks][0], qh[ks][1], qh[ks][2], qh[ks][3], ad + FQ_HI);
        LDM_X4(ql[ks][0], ql[ks][1], ql[ks][2], ql[ks][3], ad + FQ_LO);
    }

    float o[16][4];
#pragma unroll
    for (int nt = 0; nt < 16; nt++)
#pragma unroll
        for (int j = 0; j < 4; j++) o[nt][j] = 0.f;
    float m0 = -1e30f, m1 = -1e30f, l0 = 0.f, l1 = 0.f;

    const int last = 2 * qblk + 1;
    for (int kt = 0; kt <= last; kt++) {
        if (kt < last) { LOAD_KV(FSTG0 + ((kt + 1) & 1) * FSTG_SZ, kt + 1); CP_WAIT_1(); }
        else           { CP_WAIT_0(); }
        __syncthreads();

        const uint32_t stg = sb + FSTG0 + (kt & 1) * FSTG_SZ;
        const bool skip = (kt * 64) > (q0 + w * 16 + 15);
        if (!skip) {
            float s[8][4];
#pragma unroll
            for (int nt = 0; nt < 8; nt++)
#pragma unroll
                for (int j = 0; j < 4; j++) s[nt][j] = 0.f;

#pragma unroll
            for (int ks = 0; ks < 8; ks++) {
#pragma unroll
                for (int ntp = 0; ntp < 4; ntp++) {
                    int bn = ntp * 16 + (g >> 1) * 8 + r8;
                    int kc = ks * 2 + (g & 1);
                    uint32_t ad = stg + off256(bn, kc);
                    uint32_t t0, t1, t2, t3;
                    LDM_X4(t0, t1, t2, t3, ad + FK_HI);
                    uint32_t u0, u1, u2, u3;
                    LDM_X4(u0, u1, u2, u3, ad + FK_LO);
                    uint32_t bh0[2] = {t0, t1}, bh1[2] = {t2, t3};
                    uint32_t bl0[2] = {u0, u1}, bl1[2] = {u2, u3};
                    mma16816(s[2*ntp],   qh[ks], bh0);
                    mma16816(s[2*ntp],   ql[ks], bh0);
                    mma16816(s[2*ntp],   qh[ks], bl0);
                    mma16816(s[2*ntp+1], qh[ks], bh1);
                    mma16816(s[2*ntp+1], ql[ks], bh1);
                    mma16816(s[2*ntp+1], qh[ks], bl1);
                }
            }

            if (kt >= 2 * qblk) {
                int rg0 = q0 + w * 16 + (lane >> 2);
#pragma unroll
                for (int nt = 0; nt < 8; nt++) {
                    int c0 = kt * 64 + nt * 8 + (lane & 3) * 2;
                    if (c0     > rg0)     s[nt][0] = -1e30f;
                    if (c0 + 1 > rg0)     s[nt][1] = -1e30f;
                    if (c0     > rg0 + 8) s[nt][2] = -1e30f;
                    if (c0 + 1 > rg0 + 8) s[nt][3] = -1e30f;
                }
            }

            float mx0 = -1e30f, mx1 = -1e30f;
#pragma unroll
            for (int nt = 0; nt < 8; nt++) {
                mx0 = fmaxf(mx0, fmaxf(s[nt][0], s[nt][1]));
                mx1 = fmaxf(mx1, fmaxf(s[nt][2], s[nt][3]));
            }
            mx0 = fmaxf(mx0, __shfl_xor_sync(0xffffffffu, mx0, 1));
            mx0 = fmaxf(mx0, __shfl_xor_sync(0xffffffffu, mx0, 2));
            mx1 = fmaxf(mx1, __shfl_xor_sync(0xffffffffu, mx1, 1));
            mx1 = fmaxf(mx1, __shfl_xor_sync(0xffffffffu, mx1, 2));
            float nm0 = fmaxf(m0, mx0), nm1 = fmaxf(m1, mx1);
            float cr0 = ex2(m0 - nm0), cr1 = ex2(m1 - nm1);
            m0 = nm0; m1 = nm1;
            float ps0 = 0.f, ps1 = 0.f;
#pragma unroll
            for (int nt = 0; nt < 8; nt++) {
                s[nt][0] = ex2(s[nt][0] - m0);
                s[nt][1] = ex2(s[nt][1] - m0);
                s[nt][2] = ex2(s[nt][2] - m1);
                s[nt][3] = ex2(s[nt][3] - m1);
                ps0 += s[nt][0] + s[nt][1];
                ps1 += s[nt][2] + s[nt][3];
            }
            ps0 += __shfl_xor_sync(0xffffffffu, ps0, 1);
            ps0 += __shfl_xor_sync(0xffffffffu, ps0, 2);
            ps1 += __shfl_xor_sync(0xffffffffu, ps1, 1);
            ps1 += __shfl_xor_sync(0xffffffffu, ps1, 2);
            l0 = l0 * cr0 + ps0;
            l1 = l1 * cr1 + ps1;
#pragma unroll
            for (int nt = 0; nt < 16; nt++) {
                o[nt][0] *= cr0; o[nt][1] *= cr0;
                o[nt][2] *= cr1; o[nt][3] *= cr1;
            }

            uint32_t ph[4][4];
#pragma unroll
            for (int kf = 0; kf < 4; kf++) {
                ph[kf][0] = f22u(s[2*kf][0],   s[2*kf][1]);
                ph[kf][1] = f22u(s[2*kf][2],   s[2*kf][3]);
                ph[kf][2] = f22u(s[2*kf+1][0], s[2*kf+1][1]);
                ph[kf][3] = f22u(s[2*kf+1][2], s[2*kf+1][3]);
            }

#pragma unroll
            for (int kf = 0; kf < 4; kf++) {
#pragma unroll
                for (int ntp = 0; ntp < 8; ntp++) {
                    int dn = ntp * 16 + (g >> 1) * 8 + r8;
                    int ck = kf * 2 + (g & 1);
                    uint32_t ad = stg + FV_HI + off128(dn, ck);
                    uint32_t t0, t1, t2, t3;
                    LDM_X4(t0, t1, t2, t3, ad);
                    uint32_t b0[2] = {t0, t1}, b1[2] = {t2, t3};
                    mma16816(o[2*ntp],   ph[kf], b0);
                    mma16816(o[2*ntp+1], ph[kf], b1);
                    LDM_X4(t0, t1, t2, t3, ad + 16384);
                    uint32_t c0a[2] = {t0, t1}, c1a[2] = {t2, t3};
                    mma16816(o[2*ntp],   ph[kf], c0a);
                    mma16816(o[2*ntp+1], ph[kf], c1a);
                }
            }
        }
        __syncthreads();
    }

    // epilogue: normalize, write fp16 hi/lo directly (o_proj input)
    float i0 = 1.f / l0, i1 = 1.f / l1;
    int er = lane >> 2, ec = (lane & 3) * 2;
    size_t row0 = (size_t)b * SS + q0 + w * 16 + er;
    size_t o0 = row0 * (NH*DD) + (size_t)h * DD;
    size_t o1 = (row0 + 8) * (NH*DD) + (size_t)h * DD;
#pragma unroll
    for (int nt = 0; nt < 16; nt++) {
        float v0 = o[nt][0] * i0, v1 = o[nt][1] * i0;
        float v2 = o[nt][2] * i1, v3 = o[nt][3] * i1;
        __half h0 = __float2half_rn(v0), h1 = __float2half_rn(v1);
        __half h2 = __float2half_rn(v2), h3 = __float2half_rn(v3);
        *(uint32_t*)(Ohi + o0 + nt * 8 + ec) = f22u(v0, v1);
        *(uint32_t*)(Olo + o0 + nt * 8 + ec) =
            f22u(v0 - __half2float(h0), v1 - __half2float(h1));
        *(uint32_t*)(Ohi + o1 + nt * 8 + ec) = f22u(v2, v3);
        *(uint32_t*)(Olo + o1 + nt * 8 + ec) =
            f22u(v2 - __half2float(h2), v3 - __half2float(h3));
    }
    #undef LOAD_KV
}

// ---------------- launch ----------------
extern "C" void kernel_launch(void* const* d_in, const int* in_sizes, int n_in,
                              void* d_out, int out_size)
{
    const float* X    = (const float*)d_in[0];
    const float* Wq   = (const float*)d_in[1];
    const float* Wk   = (const float*)d_in[2];
    const float* Wv   = (const float*)d_in[3];
    const float* Wo   = (const float*)d_in[4];
    const float* cosc = (const float*)d_in[5];
    const float* sinc = (const float*)d_in[6];
    float* out = (float*)d_out;

    float *gq, *gk, *gv;
    __half *gXhi, *gXlo, *gAhi, *gAlo;
    __half *gWqh, *gWql, *gWkh, *gWkl, *gWvh, *gWvl, *gWoh, *gWol;
    __half *gQfh, *gQfl, *gKfh, *gKfl, *gVTh, *gVTl;
    cudaGetSymbolAddress((void**)&gq,    g_q);
    cudaGetSymbolAddress((void**)&gk,    g_k);
    cudaGetSymbolAddress((void**)&gv,    g_v);
    cudaGetSymbolAddress((void**)&gXhi,  g_Xhi);
    cudaGetSymbolAddress((void**)&gXlo,  g_Xlo);
    cudaGetSymbolAddress((void**)&gAhi,  g_Ahi);
    cudaGetSymbolAddress((void**)&gAlo,  g_Alo);
    cudaGetSymbolAddress((void**)&gWqh,  g_Wqt_hi);
    cudaGetSymbolAddress((void**)&gWql,  g_Wqt_lo);
    cudaGetSymbolAddress((void**)&gWkh,  g_Wkt_hi);
    cudaGetSymbolAddress((void**)&gWkl,  g_Wkt_lo);
    cudaGetSymbolAddress((void**)&gWvh,  g_Wvt_hi);
    cudaGetSymbolAddress((void**)&gWvl,  g_Wvt_lo);
    cudaGetSymbolAddress((void**)&gWoh,  g_Wot_hi);
    cudaGetSymbolAddress((void**)&gWol,  g_Wot_lo);
    cudaGetSymbolAddress((void**)&gQfh,  g_Qfhi);
    cudaGetSymbolAddress((void**)&gQfl,  g_Qflo);
    cudaGetSymbolAddress((void**)&gKfh,  g_Kfhi);
    cudaGetSymbolAddress((void**)&gKfl,  g_Kflo);
    cudaGetSymbolAddress((void**)&gVTh,  g_VThi);
    cudaGetSymbolAddress((void**)&gVTl,  g_VTlo);

    static bool attr_set = false;
    if (!attr_set) {
        cudaFuncSetAttribute(hgemm3_kernel, cudaFuncAttributeMaxDynamicSharedMemorySize,
                             GEMM_SMEM_TOTAL);
        cudaFuncSetAttribute(flash_mma_kernel, cudaFuncAttributeMaxDynamicSharedMemorySize,
                             FLASH_SMEM);
        attr_set = true;
    }

    // prep
    split_kernel<<<(TT*HID)/1024, 256>>>(X, gXhi, gXlo);
    transpose_split_kernel<<<dim3(HID/32, HID/32), dim3(32, 8)>>>(Wq, gWqh, gWql, HID, HID);
    transpose_split_kernel<<<dim3((NKV*DD)/32, HID/32), dim3(32, 8)>>>(Wk, gWkh, gWkl, HID, NKV*DD);
    transpose_split_kernel<<<dim3((NKV*DD)/32, HID/32), dim3(32, 8)>>>(Wv, gWvh, gWvl, HID, NKV*DD);
    transpose_split_kernel<<<dim3(HID/32, HID/32), dim3(32, 8)>>>(Wo, gWoh, gWol, HID, HID);

    // QKV projections (tensor cores)
    hgemm3_kernel<<<dim3(HID/GBN, TT/GBM), 256, GEMM_SMEM_TOTAL>>>(
        gXhi, gXlo, gWqh, gWql, gq, TT, HID, HID);
    hgemm3_kernel<<<dim3((NKV*DD)/GBN, TT/GBM), 256, GEMM_SMEM_TOTAL>>>(
        gXhi, gXlo, gWkh, gWkl, gk, TT, NKV*DD, HID);
    hgemm3_kernel<<<dim3((NKV*DD)/GBN, TT/GBM), 256, GEMM_SMEM_TOTAL>>>(
        gXhi, gXlo, gWvh, gWvl, gv, TT, NKV*DD, HID);

    // RoPE + transpose into fp16 hi/lo flash operands
    rope_q_f16<<<(TT*NH*DD)/256, 256>>>(gq, cosc, sinc, gQfh, gQfl);
    rope_k_f16<<<(TT*NKV*DD)/256, 256>>>(gk, cosc, sinc, gKfh, gKfl);
    transpose_v_f16<<<dim3(SS/32, DD/32, BB*NKV), dim3(32, 8)>>>(gv, gVTh, gVTl);

    // flash attention (tensor cores) -> writes fp16 hi/lo o_proj input directly
    flash_mma_kernel<<<dim3(SS/128, NH, BB), 256, FLASH_SMEM>>>(
        gQfh, gQfl, gKfh, gKfl, gVTh, gVTl, gAhi, gAlo);

    // o_proj (tensor cores)
    hgemm3_kernel<<<dim3(HID/GBN, TT/GBM), 256, GEMM_SMEM_TOTAL>>>(
        gAhi, gAlo, gWoh, gWol, out, TT, HID, HID);
}